// round 17
// baseline (speedup 1.0000x reference)
#include <cuda_runtime.h>
#include <cuda_bf16.h>
#include <math.h>

// Problem constants (fixed by the dataset)
#define N_NODES   100000
#define N_EDGES   1600000
#define IN_FEATS  128
#define HD        64          // NUM_HEADS * OUT_FEATS = 4*16
#define NUM_HEADS 4
#define OUT_FEATS 16
#define EDGE_FEATS 32
#define NUM_ETYPES 8
#define NEG_SLOPE 0.2f

#define SBLK  512
#define NSBLK ((N_NODES + SBLK - 1) / SBLK)   // 196
#define E4    (N_EDGES / 4)                    // 400000 int4 groups
#define E4_BLOCKS ((E4 + 255) / 256)           // ceil-div grid
#define FBLK  64                               // nodes per feat block (3 blocks/SM)
#define NFBLK ((N_NODES + FBLK - 1) / FBLK)    // 1563

// feat_kernel dynamic smem layout (floats): xs + wt + al + ar  (~66 KB)
#define FEAT_SMEM_FLOATS (FBLK * IN_FEATS + IN_FEATS * HD + 2 * HD)
#define FEAT_SMEM_BYTES  (FEAT_SMEM_FLOATS * 4)

// ---------------- static device scratch (no allocations allowed) -------------
__device__ __align__(16) float  g_feat[N_NODES * HD];     // projected features [N,64]
__device__ __align__(16) float  g_el[N_NODES * NUM_HEADS];
__device__ __align__(16) float  g_er[N_NODES * NUM_HEADS];
__device__ __align__(16) float  g_ee[NUM_ETYPES * NUM_HEADS];  // [et][h]
__device__ int    g_count[N_NODES];
__device__ int    g_off[N_NODES + 1];
__device__ int    g_cursor[N_NODES];
__device__ int    g_csr[N_EDGES];                         // src | (etype<<17), CSR order
__device__ int    g_bsum[NSBLK];

// ---------------- K1: histogram of dst (4 edges/thread, int4 loads) ---------
__global__ void hist_kernel(const int* __restrict__ dst) {
    int t = blockIdx.x * blockDim.x + threadIdx.x;
    if (t >= E4) return;
    int4 d = ((const int4*)dst)[t];
    atomicAdd(&g_count[d.x], 1);
    atomicAdd(&g_count[d.y], 1);
    atomicAdd(&g_count[d.z], 1);
    atomicAdd(&g_count[d.w], 1);
}

// ---------------- K2a: per-block inclusive scan of counts -------------------
__global__ __launch_bounds__(SBLK) void scan1_kernel() {
    __shared__ int sm[SBLK];
    int t = threadIdx.x;
    int i = blockIdx.x * SBLK + t;
    int c = (i < N_NODES) ? g_count[i] : 0;
    sm[t] = c;
    __syncthreads();
    #pragma unroll
    for (int off = 1; off < SBLK; off <<= 1) {
        int v = (t >= off) ? sm[t - off] : 0;
        __syncthreads();
        sm[t] += v;
        __syncthreads();
    }
    if (i < N_NODES) g_off[i] = sm[t] - c;     // block-local exclusive
    if (t == SBLK - 1) g_bsum[blockIdx.x] = sm[t];
}

// ---------------- K2b: merged scan of block sums + fix-up + cursor init -----
__global__ __launch_bounds__(SBLK) void scan23_kernel() {
    __shared__ int bs[SBLK];
    int t = threadIdx.x;
    int myb = g_bsum[blockIdx.x];              // read before smem scan
    bs[t] = (t < NSBLK) ? g_bsum[t] : 0;
    __syncthreads();
    #pragma unroll
    for (int off = 1; off < SBLK; off <<= 1) {
        int v = (t >= off) ? bs[t - off] : 0;
        __syncthreads();
        bs[t] += v;
        __syncthreads();
    }
    int prefix = bs[blockIdx.x] - myb;         // exclusive prefix of this block
    int i = blockIdx.x * SBLK + t;
    if (i < N_NODES) {
        int o = g_off[i] + prefix;
        g_off[i] = o;
        g_cursor[i] = o;
    }
    if (blockIdx.x == NSBLK - 1 && t == 0) g_off[N_NODES] = bs[NSBLK - 1];
}

// ---------------- K3: position-only scatter, 4B per edge (dst not needed) ----
__global__ void scatter_lite_kernel(const int* __restrict__ src,
                                    const int* __restrict__ dst,
                                    const int* __restrict__ etype) {
    int t = blockIdx.x * blockDim.x + threadIdx.x;
    if (t >= E4) return;
    int4 s4  = ((const int4*)src)[t];
    int4 d4  = ((const int4*)dst)[t];
    int4 et4 = ((const int4*)etype)[t];
    int p;
    p = atomicAdd(&g_cursor[d4.x], 1); g_csr[p] = s4.x | (et4.x << 17);
    p = atomicAdd(&g_cursor[d4.y], 1); g_csr[p] = s4.y | (et4.y << 17);
    p = atomicAdd(&g_cursor[d4.z], 1); g_csr[p] = s4.z | (et4.z << 17);
    p = atomicAdd(&g_cursor[d4.w], 1); g_csr[p] = s4.w | (et4.w << 17);
}

// ---------------- K4: register-tiled SGEMM feat = x @ fc_w^T + el/er + ee ----
// 256 threads, 64 nodes/block, ~66 KB dynamic smem -> 3 blocks/SM (24 warps).
// Thread (tx,ty): tx=tid&15 -> cols tx*4..tx*4+3 (head tx>>2); ty=tid>>4 ->
// nodes ty*4..ty*4+3.
__global__ __launch_bounds__(256) void feat_kernel(
        const float* __restrict__ x,
        const float* __restrict__ fc_w,
        const float* __restrict__ attn_l,
        const float* __restrict__ attn_r,
        const float* __restrict__ edge_emb,
        const float* __restrict__ fc_e_w,
        const float* __restrict__ attn_e) {
    extern __shared__ float smem[];
    float* xs = smem;                              // [FBLK][IN_FEATS]
    float* wt = smem + FBLK * IN_FEATS;            // [IN_FEATS][HD]
    float* al = wt + IN_FEATS * HD;                // [HD]
    float* ar = al + HD;                           // [HD]

    int tid = threadIdx.x;
    int tx = tid & 15;
    int ty = tid >> 4;

    // ee[t][h] table: computed once by block 0's first warp
    if (blockIdx.x == 0 && tid < NUM_ETYPES * NUM_HEADS) {
        int et = tid & (NUM_ETYPES - 1);
        int h  = tid >> 3;
        const float* emb = edge_emb + et * EDGE_FEATS;
        float s = 0.f;
        for (int fe = 0; fe < EDGE_FEATS; fe++) {
            const float* wrow = fc_e_w + (h * EDGE_FEATS + fe) * EDGE_FEATS;
            float proj = 0.f;
            #pragma unroll 8
            for (int j = 0; j < EDGE_FEATS; j++) proj += emb[j] * wrow[j];
            s += proj * attn_e[h * EDGE_FEATS + fe];
        }
        g_ee[et * NUM_HEADS + h] = s;
    }

    // load fc_w transposed: fc_w[j*128+k] -> wt[k*HD+j]
    for (int i = tid; i < HD * IN_FEATS; i += 256) {
        int j = i >> 7, k = i & 127;
        wt[k * HD + j] = fc_w[i];
    }
    if (tid < HD) { al[tid] = attn_l[tid]; ar[tid] = attn_r[tid]; }

    // load 64 node rows, float4-coalesced; OOB nodes read row 0 (stores guarded)
    long long nbase = (long long)blockIdx.x * FBLK;
    for (int i = tid; i < FBLK * (IN_FEATS / 4); i += 256) {
        int n = i >> 5, k4 = i & 31;
        long long gn = nbase + n;
        const float4* srcp = (const float4*)(x + (gn < N_NODES ? gn : 0) * IN_FEATS);
        ((float4*)(xs + n * IN_FEATS))[k4] = srcp[k4];
    }
    __syncthreads();

    float acc[4][4];
    #pragma unroll
    for (int i = 0; i < 4; i++)
        #pragma unroll
        for (int c = 0; c < 4; c++) acc[i][c] = 0.f;

    #pragma unroll 4
    for (int k4 = 0; k4 < IN_FEATS / 4; k4++) {
        float4 wv0 = *(const float4*)&wt[(k4 * 4 + 0) * HD + tx * 4];
        float4 wv1 = *(const float4*)&wt[(k4 * 4 + 1) * HD + tx * 4];
        float4 wv2 = *(const float4*)&wt[(k4 * 4 + 2) * HD + tx * 4];
        float4 wv3 = *(const float4*)&wt[(k4 * 4 + 3) * HD + tx * 4];
        #pragma unroll
        for (int i = 0; i < 4; i++) {
            float4 xv = ((const float4*)(xs + (ty * 4 + i) * IN_FEATS))[k4];
            acc[i][0] = fmaf(xv.x, wv0.x, acc[i][0]);
            acc[i][1] = fmaf(xv.x, wv0.y, acc[i][1]);
            acc[i][2] = fmaf(xv.x, wv0.z, acc[i][2]);
            acc[i][3] = fmaf(xv.x, wv0.w, acc[i][3]);
            acc[i][0] = fmaf(xv.y, wv1.x, acc[i][0]);
            acc[i][1] = fmaf(xv.y, wv1.y, acc[i][1]);
            acc[i][2] = fmaf(xv.y, wv1.z, acc[i][2]);
            acc[i][3] = fmaf(xv.y, wv1.w, acc[i][3]);
            acc[i][0] = fmaf(xv.z, wv2.x, acc[i][0]);
            acc[i][1] = fmaf(xv.z, wv2.y, acc[i][1]);
            acc[i][2] = fmaf(xv.z, wv2.z, acc[i][2]);
            acc[i][3] = fmaf(xv.z, wv2.w, acc[i][3]);
            acc[i][0] = fmaf(xv.w, wv3.x, acc[i][0]);
            acc[i][1] = fmaf(xv.w, wv3.y, acc[i][1]);
            acc[i][2] = fmaf(xv.w, wv3.z, acc[i][2]);
            acc[i][3] = fmaf(xv.w, wv3.w, acc[i][3]);
        }
    }

    // epilogue: store feat rows (float4, coalesced) + el/er dots
    float4 av = *(const float4*)&al[tx * 4];
    float4 rv = *(const float4*)&ar[tx * 4];
    int h = tx >> 2;                           // head for this thread's 4 cols
    #pragma unroll
    for (int i = 0; i < 4; i++) {
        long long n = nbase + ty * 4 + i;
        bool ok = (n < N_NODES);
        if (ok)
            *(float4*)&g_feat[n * HD + tx * 4] =
                make_float4(acc[i][0], acc[i][1], acc[i][2], acc[i][3]);
        float pl = acc[i][0] * av.x + acc[i][1] * av.y
                 + acc[i][2] * av.z + acc[i][3] * av.w;
        float pr = acc[i][0] * rv.x + acc[i][1] * rv.y
                 + acc[i][2] * rv.z + acc[i][3] * rv.w;
        // reduce over the 4 tx-lanes of this head (lane bits 0,1 == tx bits 0,1)
        pl += __shfl_xor_sync(0xFFFFFFFFu, pl, 1);
        pl += __shfl_xor_sync(0xFFFFFFFFu, pl, 2);
        pr += __shfl_xor_sync(0xFFFFFFFFu, pr, 1);
        pr += __shfl_xor_sync(0xFFFFFFFFu, pr, 2);
        if ((tx & 3) == 0 && ok) {
            g_el[n * 4 + h] = pl;
            g_er[n * 4 + h] = pr;
        }
    }
}

// ---------------- K5: per-dst FUSED softmax + gather --------------------------
// One warp per dst node; lane covers output cols {2*lane, 2*lane+1} (head
// lane>>3). Per 32-edge tile, lane i does edge i's logit/leaky/exp (scattered
// el4[src] gather, edge-parallel) and stages 4 exps to smem. Gather loop:
// 1 shfl (src) + 1 LDS (p) + 1 scattered LDG.64 per edge. Pads stage zeros.
__global__ __launch_bounds__(256) void aggregate_kernel(float* __restrict__ out) {
    __shared__ float4 sh_ex[8][32];            // 4 KB
    __shared__ float  see[NUM_ETYPES * NUM_HEADS];
    int tid = threadIdx.x;
    if (tid < NUM_ETYPES * NUM_HEADS) see[tid] = g_ee[tid];
    __syncthreads();

    int warp = tid >> 5, lane = tid & 31;
    int n = blockIdx.x * 8 + warp;
    if (n >= N_NODES) return;

    float2* out2 = (float2*)out;
    int beg = g_off[n];
    int deg = g_off[n + 1] - beg;
    if (deg == 0) {
        out2[n * 32 + lane] = make_float2(0.f, 0.f);
        return;
    }
    int hsel = lane >> 3;                      // head for this lane's 2 columns
    float4 ern = __ldg(((const float4*)g_er) + n);
    const float* exf = (const float*)&sh_ex[warp][0];

    float denom = 0.f;
    float2 acc = make_float2(0.f, 0.f);

    for (int tb = 0; tb < deg; tb += 32) {
        int tl = min(32, deg - tb);
        int edx = 0;
        float4 e4 = make_float4(0.f, 0.f, 0.f, 0.f);
        if (lane < tl) {
            edx = __ldg(g_csr + beg + tb + lane);
            int s  = edx & 0x1FFFF;
            int et = edx >> 17;
            float4 el = __ldg(((const float4*)g_el) + s);
            float e0 = el.x + ern.x + see[et * 4 + 0];
            float e1 = el.y + ern.y + see[et * 4 + 1];
            float e2 = el.z + ern.z + see[et * 4 + 2];
            float e3 = el.w + ern.w + see[et * 4 + 3];
            e0 = e0 > 0.f ? e0 : NEG_SLOPE * e0;
            e1 = e1 > 0.f ? e1 : NEG_SLOPE * e1;
            e2 = e2 > 0.f ? e2 : NEG_SLOPE * e2;
            e3 = e3 > 0.f ? e3 : NEG_SLOPE * e3;
            e4 = make_float4(__expf(e0), __expf(e1), __expf(e2), __expf(e3));
        }
        __syncwarp();
        sh_ex[warp][lane] = e4;
        __syncwarp();

        int tl_pad = (tl + 7) & ~7;            // pads contribute p=0, s=0
        for (int j = 0; j < tl_pad; j += 8) {
            int s[8]; float p[8]; float2 f[8];
            #pragma unroll
            for (int k = 0; k < 8; k++) {
                s[k] = __shfl_sync(0xFFFFFFFFu, edx, j + k) & 0x1FFFF;
                p[k] = exf[(j + k) * 4 + hsel];
            }
            #pragma unroll
            for (int k = 0; k < 8; k++)
                f[k] = __ldg(((const float2*)(g_feat + s[k] * HD)) + lane);
            #pragma unroll
            for (int k = 0; k < 8; k++) {
                denom += p[k];
                acc.x = fmaf(p[k], f[k].x, acc.x);
                acc.y = fmaf(p[k], f[k].y, acc.y);
            }
        }
    }

    float inv = 1.f / denom;
    out2[n * 32 + lane] = make_float2(acc.x * inv, acc.y * inv);
}

// ---------------- launch ------------------------------------------------------
// side = memset/hist/scan1/scan23/scatter_lite; main = feat (el/er epilogue).
// Join. Fused aggregate.
extern "C" void kernel_launch(void* const* d_in, const int* in_sizes, int n_in,
                              void* d_out, int out_size) {
    const float* x        = (const float*)d_in[0];
    const int*   src      = (const int*)d_in[1];
    const int*   dst      = (const int*)d_in[2];
    const int*   etype    = (const int*)d_in[3];
    const float* fc_w     = (const float*)d_in[4];
    const float* fc_e_w   = (const float*)d_in[5];
    const float* edge_emb = (const float*)d_in[6];
    const float* attn_l   = (const float*)d_in[7];
    const float* attn_r   = (const float*)d_in[8];
    const float* attn_e   = (const float*)d_in[9];
    float* out = (float*)d_out;

    static bool attr_set = false;
    if (!attr_set) {
        cudaFuncSetAttribute(feat_kernel,
                             cudaFuncAttributeMaxDynamicSharedMemorySize,
                             FEAT_SMEM_BYTES);
        attr_set = true;
    }

    void* cntPtr = nullptr;
    cudaGetSymbolAddress(&cntPtr, g_count);

    cudaStream_t side = 0;
    cudaEvent_t evFork = 0, evJoin = 0;
    bool forked =
        (cudaStreamCreateWithFlags(&side, cudaStreamNonBlocking) == cudaSuccess) &&
        (cudaEventCreateWithFlags(&evFork, cudaEventDisableTiming) == cudaSuccess) &&
        (cudaEventCreateWithFlags(&evJoin, cudaEventDisableTiming) == cudaSuccess);

    if (forked && cudaEventRecord(evFork, 0) == cudaSuccess &&
        cudaStreamWaitEvent(side, evFork, 0) == cudaSuccess) {
        // side stream: full CSR build including position scatter
        cudaMemsetAsync(cntPtr, 0, N_NODES * sizeof(int), side);
        hist_kernel<<<E4_BLOCKS, 256, 0, side>>>(dst);
        scan1_kernel<<<NSBLK, SBLK, 0, side>>>();
        scan23_kernel<<<NSBLK, SBLK, 0, side>>>();
        scatter_lite_kernel<<<E4_BLOCKS, 256, 0, side>>>(src, dst, etype);
        cudaEventRecord(evJoin, side);
        // main stream: dense projection (runs concurrently)
        feat_kernel<<<NFBLK, 256, FEAT_SMEM_BYTES>>>(x, fc_w, attn_l, attn_r,
                                                     edge_emb, fc_e_w, attn_e);
        cudaStreamWaitEvent(0, evJoin, 0);
    } else {
        // fallback: fully serial on capture stream
        cudaMemsetAsync(cntPtr, 0, N_NODES * sizeof(int), 0);
        hist_kernel<<<E4_BLOCKS, 256>>>(dst);
        scan1_kernel<<<NSBLK, SBLK>>>();
        scan23_kernel<<<NSBLK, SBLK>>>();
        scatter_lite_kernel<<<E4_BLOCKS, 256>>>(src, dst, etype);
        feat_kernel<<<NFBLK, 256, FEAT_SMEM_BYTES>>>(x, fc_w, attn_l, attn_r,
                                                     edge_emb, fc_e_w, attn_e);
    }

    aggregate_kernel<<<(N_NODES + 7) / 8, 256>>>(out);

    if (side)   cudaStreamDestroy(side);
    if (evFork) cudaEventDestroy(evFork);
    if (evJoin) cudaEventDestroy(evJoin);
}